// round 15
// baseline (speedup 1.0000x reference)
#include <cuda_runtime.h>
#include <math.h>

#define NB 8
#define NT 16384
#define NQ 256
#define NR 64
#define ND 64
#define NS 256
#define NL 20
#define OUTW 14337
#define OUTW_PAD 14368
#define TT 256
#define AS 260   // act row stride (16B-aligned rows, conflict-free)
#define DS 68    // dwT row stride (16B-aligned rows)

typedef unsigned long long ull;

__device__ __forceinline__ ull pack2(float x) {
    ull r; asm("mov.b64 %0, {%1, %1};" : "=l"(r) : "f"(x)); return r;
}
__device__ __forceinline__ ull pack2(float lo, float hi) {
    ull r; asm("mov.b64 %0, {%1, %2};" : "=l"(r) : "f"(lo), "f"(hi)); return r;
}
__device__ __forceinline__ void fma2(ull& d, ull a, ull b) {
    asm("fma.rn.f32x2 %0, %1, %2, %0;" : "+l"(d) : "l"(a), "l"(b));
}
__device__ __forceinline__ float2 u2f(ull v) {
    float2 f; asm("mov.b64 {%0, %1}, %2;" : "=f"(f.x), "=f"(f.y) : "l"(v)); return f;
}

// Scratch (device globals; no allocation allowed)
__device__ float g_h0[NB * NR * NT];
__device__ float g_h1[NB * NR * NT];
__device__ float g_acts[NL * NB * NR * OUTW_PAD];   // gated activations per layer (skip inputs)
__device__ float g_fgT[NL * 16384];                 // [li][f/g][k][r][dc] -- smem-ready
__device__ float g_dwTg[NL * 4096];                 // [li][dcc][r]
__device__ float g_swT[NL * ND * NS];               // [k=li*64+dc][s]
__device__ float g_sbsum[NS];
__device__ float g_w1T[NS * NS];
__device__ float g_w2T[NQ * NS];

// fgT[li][k*4096 + r*64 + dc] = fw[li][dc][r][k]; g at +8192
__global__ void fgw_prep(const float* __restrict__ fw, const float* __restrict__ gw,
                         float* __restrict__ fgT) {
    int li = blockIdx.y;
    int i = blockIdx.x * 256 + threadIdx.x;    // 0..8191
    int k = i >> 12, r = (i >> 6) & 63, dc = i & 63;
    int src = li * 8192 + dc * 128 + r * 2 + k;
    fgT[li * 16384 + i] = fw[src];
    fgT[li * 16384 + 8192 + i] = gw[src];
}

// dwTg[li][dcc*64 + r] = dw[li][r][dcc]
__global__ void dw_prep(const float* __restrict__ dw, float* __restrict__ dwTg) {
    int li = blockIdx.y;
    int i = blockIdx.x * 256 + threadIdx.x;    // 0..4095
    int dcc = i >> 6, r = i & 63;
    dwTg[li * 4096 + i] = dw[li * 4096 + r * 64 + dcc];
}

// wT[k][s] = w[s][k], 256x256
__global__ void transpose_kernel(const float* __restrict__ w, float* __restrict__ wT) {
    int i = blockIdx.x * 256 + threadIdx.x;
    int k = i >> 8, s = i & 255;
    wT[i] = w[(s << 8) + k];
}

// swT[k][s] = skip_w[li][s][dc], k = li*64+dc
__global__ void skipw_kernel(const float* __restrict__ sw, float* __restrict__ swT) {
    int k = blockIdx.x;          // 0..1279
    int s = threadIdx.x;         // 0..255
    int li = k >> 6, dc = k & 63;
    swT[k * NS + s] = sw[li * (NS * ND) + s * ND + dc];
}

// sbsum[s] = sum_li skip_b[li][s]
__global__ void sbsum_kernel(const float* __restrict__ sb, float* __restrict__ sbsum) {
    int s = threadIdx.x;
    float v = 0.f;
    #pragma unroll
    for (int li = 0; li < NL; li++) v += sb[li * NS + s];
    sbsum[s] = v;
}

// h[b][r][t] = cw[r][x[b,t]][0] + cw[r][x[b,t+1]][1] + cb[r]   (one-hot conv == gather)
__global__ void __launch_bounds__(256) causal_kernel(
    const int* __restrict__ x, const float* __restrict__ cw,
    const float* __restrict__ cb, float* __restrict__ h)
{
    extern __shared__ float sm[];               // 32768 floats: cw [r][q][k]
    __shared__ float cbS[64];
    for (int i = threadIdx.x; i < NR * NQ * 2; i += 256) sm[i] = cw[i];
    if (threadIdx.x < 64) cbS[threadIdx.x] = cb[threadIdx.x];
    __syncthreads();
    int b = blockIdx.y;
    int t = blockIdx.x * 256 + threadIdx.x;
    if (t >= NT - 1) return;
    int q0 = x[b * NT + t] * 2;
    int q1 = x[b * NT + t + 1] * 2 + 1;
    float* hp = h + ((size_t)b << 20) + t;
    #pragma unroll 4
    for (int r = 0; r < 64; r++) {
        hp[r << 14] = sm[(r << 9) + q0] + sm[(r << 9) + q1] + cbS[r];
    }
}

// Fused WaveNet layer (no skip), 1024 threads, 256 time cols per CTA.
// Weights pre-transposed in global -> staging is pure float4 copies.
// Phase 1: thread tile = 4 channels x 4 time cols (channel-packed weights).
// Phase 2: thread tile = 4 r x 4 time cols (time-packed, dwT transposed).
__global__ void __launch_bounds__(1024) layer_kernel(
    const float* __restrict__ hcur, float* __restrict__ hnext,
    const float* __restrict__ fgT, const float* __restrict__ fb,
    const float* __restrict__ gb,
    const float* __restrict__ dwTg, const float* __restrict__ db,
    float* __restrict__ acts,
    int li, int dil, int Lh, int Ti, int off)
{
    extern __shared__ float smem[];
    float* wfT = smem;
    float* wgT = smem + 8192;
    float* act = smem;              // [64][260], valid after phase1
    float* dwT = smem + 16640;
    float* hA  = smem + 20992;
    float* hB  = smem + 37376;

    const int tid = threadIdx.x;
    const int b = blockIdx.y;
    const int t0 = blockIdx.x * TT;

    // stage weights: contiguous float4 copies (pre-transposed in global)
    {
        const float4* src = (const float4*)(fgT + li * 16384);
        float4* dst = (float4*)smem;
        #pragma unroll
        for (int j = 0; j < 4; j++)
            dst[tid + (j << 10)] = src[tid + (j << 10)];
    }
    {
        // dwTg [dcc][r] -> smem dwT rows of stride DS (16B-aligned scatter)
        float4 v = ((const float4*)(dwTg + li * 4096))[tid & 1023];
        if (tid < 1024) {
            int dcc = tid >> 4, r4 = (tid & 15) << 2;
            *(float4*)(dwT + dcc * DS + r4) = v;
        }
    }

    const float* hbase = hcur + ((size_t)b << 20);
    #pragma unroll 1
    for (int i = tid << 1; i < 64 * TT; i += 2048) {
        int r = i >> 8, tt = i & 255;
        int ta = t0 + tt;
        float2 va, vb;
        if (ta + 1 < Lh) {
            va = *(const float2*)(hbase + (r << 14) + ta);
        } else {
            va.x = (ta < Lh) ? hbase[(r << 14) + ta] : 0.f;
            va.y = 0.f;
        }
        int tb = ta + dil;
        vb.x = (tb < Lh) ? hbase[(r << 14) + tb] : 0.f;
        vb.y = (tb + 1 < Lh) ? hbase[(r << 14) + tb + 1] : 0.f;
        *(float2*)(hA + i) = va;
        *(float2*)(hB + i) = vb;
    }
    __syncthreads();

    // ---- Phase 1: filter/gate GEMM (K=64, 2 taps) ----
    const int cg = tid & 63;
    const int dg = tid >> 6;         // 0..15
    const int dc0 = dg << 2;
    ull facc[2][4], gacc[2][4];      // [channel pair][col], channel-packed
    {
        ull fbp0 = pack2(fb[dc0], fb[dc0 + 1]);
        ull fbp1 = pack2(fb[dc0 + 2], fb[dc0 + 3]);
        ull gbp0 = pack2(gb[dc0], gb[dc0 + 1]);
        ull gbp1 = pack2(gb[dc0 + 2], gb[dc0 + 3]);
        #pragma unroll
        for (int c = 0; c < 4; c++) {
            facc[0][c] = fbp0; facc[1][c] = fbp1;
            gacc[0][c] = gbp0; gacc[1][c] = gbp1;
        }
        const float* hap = hA + (cg << 2);
        const float* hbp = hB + (cg << 2);
        #pragma unroll 2
        for (int r = 0; r < 64; r++) {
            float4 A = *(const float4*)(hap + (r << 8));
            float4 C = *(const float4*)(hbp + (r << 8));
            ull a[4], c2[4];
            a[0] = pack2(A.x); a[1] = pack2(A.y); a[2] = pack2(A.z); a[3] = pack2(A.w);
            c2[0] = pack2(C.x); c2[1] = pack2(C.y); c2[2] = pack2(C.z); c2[3] = pack2(C.w);
            {
                ulonglong2 W0 = *(const ulonglong2*)(wfT + (r << 6) + dc0);
                ulonglong2 W1 = *(const ulonglong2*)(wfT + 4096 + (r << 6) + dc0);
                #pragma unroll
                for (int c = 0; c < 4; c++) {
                    fma2(facc[0][c], W0.x, a[c]);
                    fma2(facc[1][c], W0.y, a[c]);
                    fma2(facc[0][c], W1.x, c2[c]);
                    fma2(facc[1][c], W1.y, c2[c]);
                }
            }
            {
                ulonglong2 W0 = *(const ulonglong2*)(wgT + (r << 6) + dc0);
                ulonglong2 W1 = *(const ulonglong2*)(wgT + 4096 + (r << 6) + dc0);
                #pragma unroll
                for (int c = 0; c < 4; c++) {
                    fma2(gacc[0][c], W0.x, a[c]);
                    fma2(gacc[1][c], W0.y, a[c]);
                    fma2(gacc[0][c], W1.x, c2[c]);
                    fma2(gacc[1][c], W1.y, c2[c]);
                }
            }
        }
        // out = tanh(f) * sigmoid(g)
        #pragma unroll
        for (int p = 0; p < 2; p++) {
            #pragma unroll
            for (int c = 0; c < 4; c++) {
                float2 f = u2f(facc[p][c]);
                float2 g = u2f(gacc[p][c]);
                float ef0 = __expf(fminf(-2.f * f.x, 80.f));
                float ef1 = __expf(fminf(-2.f * f.y, 80.f));
                float eg0 = __expf(fminf(-g.x, 80.f));
                float eg1 = __expf(fminf(-g.y, 80.f));
                float o0 = __fdividef(1.f - ef0, (1.f + ef0) * (1.f + eg0));
                float o1 = __fdividef(1.f - ef1, (1.f + ef1) * (1.f + eg1));
                facc[p][c] = pack2(o0, o1);
            }
        }
    }
    __syncthreads();    // all wfT/wgT/hA reads done

    // write activation tile (STS.128, conflict-free)
    {
        float2 v0 = u2f(facc[0][0]), v1 = u2f(facc[0][1]),
               v2 = u2f(facc[0][2]), v3 = u2f(facc[0][3]);
        float2 w0 = u2f(facc[1][0]), w1 = u2f(facc[1][1]),
               w2 = u2f(facc[1][2]), w3 = u2f(facc[1][3]);
        float* rbase = act + dc0 * AS + (cg << 2);
        *(float4*)(rbase)          = make_float4(v0.x, v1.x, v2.x, v3.x);
        *(float4*)(rbase + AS)     = make_float4(v0.y, v1.y, v2.y, v3.y);
        *(float4*)(rbase + 2 * AS) = make_float4(w0.x, w1.x, w2.x, w3.x);
        *(float4*)(rbase + 3 * AS) = make_float4(w0.y, w1.y, w2.y, w3.y);
    }
    __syncthreads();

    // store act tile to global (skip input), cols >= off, aligned to skip index
    {
        float* abase = acts + (size_t)((li * NB + b) * 64) * OUTW_PAD - off;
        #pragma unroll 1
        for (int i = tid; i < 64 * TT; i += 1024) {
            int dcw = i >> 8, tt = i & 255;
            int tgl = t0 + tt;
            if (tgl >= off && tgl < Ti)
                abase[(size_t)dcw * OUTW_PAD + tgl] = act[dcw * AS + tt];
        }
    }

    const int tl = tid & 31;
    const int wp = tid >> 5;   // 0..31

    // ---- Phase 2: dense 1x1 (D->R) + residual -> hnext, 4r x 4cols ----
    {
        const int rg = wp >> 1;            // 0..15
        const int half = wp & 1;
        const int r0 = rg << 2;
        const int c0 = (half << 7) + (tl << 2);
        ull acc[4][2];
        #pragma unroll
        for (int m = 0; m < 4; m++) {
            ull dbv = pack2(db[r0 + m]);
            acc[m][0] = dbv; acc[m][1] = dbv;
        }
        #pragma unroll 1
        for (int dcc = 0; dcc < 64; dcc++) {
            ulonglong2 o = *(const ulonglong2*)(act + dcc * AS + c0);
            float4 w4 = *(const float4*)(dwT + dcc * DS + r0);   // broadcast
            ull w0 = pack2(w4.x), w1 = pack2(w4.y), w2 = pack2(w4.z), w3 = pack2(w4.w);
            fma2(acc[0][0], w0, o.x); fma2(acc[0][1], w0, o.y);
            fma2(acc[1][0], w1, o.x); fma2(acc[1][1], w1, o.y);
            fma2(acc[2][0], w2, o.x); fma2(acc[2][1], w2, o.y);
            fma2(acc[3][0], w3, o.x); fma2(acc[3][1], w3, o.y);
        }
        float* hnb = hnext + ((size_t)b << 20);
        const int tgl = t0 + c0;
        #pragma unroll
        for (int m = 0; m < 4; m++) {
            int r = r0 + m;
            float4 hv = *(const float4*)(hB + (r << 8) + c0);
            float2 v0 = u2f(acc[m][0]);
            float2 v1 = u2f(acc[m][1]);
            float4 v = make_float4(v0.x + hv.x, v0.y + hv.y, v1.x + hv.z, v1.y + hv.w);
            if (tgl + 3 < Ti) {
                *(float4*)(hnb + (r << 14) + tgl) = v;
            } else {
                if (tgl < Ti)     hnb[(r << 14) + tgl]     = v.x;
                if (tgl + 1 < Ti) hnb[(r << 14) + tgl + 1] = v.y;
                if (tgl + 2 < Ti) hnb[(r << 14) + tgl + 2] = v.z;
            }
        }
    }
}

// Fused post chain: total(K=1280 GEMM over acts) -> +sbsum,relu -> pp1(K=256)
//   -> +b1,relu -> pp2(K=256) -> +b2 -> out.   1024 threads, 128 time cols/CTA.
// Thread tile: 8 s x 4 consecutive t (time-packed); weights broadcast LDS.128.
// smem: inS [64][128]=8192, wS [64][256]=16384, buf [256][128]=32768 -> 57344 floats
__global__ void __launch_bounds__(1024) fused_post_kernel(
    const float* __restrict__ acts, const float* __restrict__ swT,
    const float* __restrict__ sbsum,
    const float* __restrict__ w1T, const float* __restrict__ b1,
    const float* __restrict__ w2T, const float* __restrict__ b2,
    float* __restrict__ outp)
{
    extern __shared__ float smem[];
    float* inS = smem;            // [64][128]
    float* wS  = smem + 8192;     // [64][256]
    float* buf = smem + 24576;    // [256][128]
    const int tid = threadIdx.x;
    const int b = blockIdx.y;
    const int t0 = blockIdx.x << 7;
    const int tl = tid & 31;
    const int wp = tid >> 5;      // 0..31
    const int s0 = wp << 3;       // 8 s per thread (broadcast weight quads in warp)
    const int c0 = tl << 2;       // 4 consecutive t per lane
    const bool fullTile = (t0 + 127 < OUTW);

    ull acc[8][2];

    // ---- Stage A: skip GEMM, K = 20 layers x 64 channels ----
    #pragma unroll
    for (int m = 0; m < 8; m++) { acc[m][0] = 0ULL; acc[m][1] = 0ULL; }

    #pragma unroll 1
    for (int li = 0; li < NL; li++) {
        __syncthreads();
        const float* ab = acts + (size_t)((li * NB + b) * 64) * OUTW_PAD;
        if (fullTile) {
            int i = tid << 3;
            int dcr = i >> 7, tt = i & 127;
            const float* src = ab + (size_t)dcr * OUTW_PAD + t0 + tt;
            *(float4*)(inS + i)     = *(const float4*)(src);
            *(float4*)(inS + i + 4) = *(const float4*)(src + 4);
        } else {
            #pragma unroll 1
            for (int i = tid; i < 8192; i += 1024) {
                int dcr = i >> 7, tt = i & 127;
                int t = t0 + tt;
                inS[i] = (t < OUTW) ? ab[(size_t)dcr * OUTW_PAD + t] : 0.f;
            }
        }
        {
            int i = tid << 4;
            const float* src = swT + li * 16384 + i;
            #pragma unroll
            for (int j = 0; j < 4; j++)
                *(float4*)(wS + i + (j << 2)) = *(const float4*)(src + (j << 2));
        }
        __syncthreads();
        #pragma unroll 1
        for (int kk = 0; kk < 64; kk++) {
            ulonglong2 o = *(const ulonglong2*)(inS + (kk << 7) + c0);
            const float* wr = wS + (kk << 8) + s0;
            float4 wa = *(const float4*)(wr);       // broadcast
            float4 wb = *(const float4*)(wr + 4);   // broadcast
            ull w;
            w = pack2(wa.x); fma2(acc[0][0], w, o.x); fma2(acc[0][1], w, o.y);
            w = pack2(wa.y); fma2(acc[1][0], w, o.x); fma2(acc[1][1], w, o.y);
            w = pack2(wa.z); fma2(acc[2][0], w, o.x); fma2(acc[2][1], w, o.y);
            w = pack2(wa.w); fma2(acc[3][0], w, o.x); fma2(acc[3][1], w, o.y);
            w = pack2(wb.x); fma2(acc[4][0], w, o.x); fma2(acc[4][1], w, o.y);
            w = pack2(wb.y); fma2(acc[5][0], w, o.x); fma2(acc[5][1], w, o.y);
            w = pack2(wb.z); fma2(acc[6][0], w, o.x); fma2(acc[6][1], w, o.y);
            w = pack2(wb.w); fma2(acc[7][0], w, o.x); fma2(acc[7][1], w, o.y);
        }
    }
    // total + biasSum, relu -> buf
    #pragma unroll
    for (int m = 0; m < 8; m++) {
        float sbv = sbsum[s0 + m];
        float2 v0 = u2f(acc[m][0]);
        float2 v1 = u2f(acc[m][1]);
        float4 v = make_float4(fmaxf(v0.x + sbv, 0.f), fmaxf(v0.y + sbv, 0.f),
                               fmaxf(v1.x + sbv, 0.f), fmaxf(v1.y + sbv, 0.f));
        *(float4*)(buf + ((s0 + m) << 7) + c0) = v;
    }

    // ---- Stage B: pp1 (K=256) ----
    #pragma unroll
    for (int m = 0; m < 8; m++) {
        ull bv = pack2(b1[s0 + m]);
        acc[m][0] = bv; acc[m][1] = bv;
    }
    #pragma unroll 1
    for (int kc = 0; kc < 4; kc++) {
        __syncthreads();
        {
            int i = tid << 4;
            const float* src = w1T + (kc << 14) + i;
            #pragma unroll
            for (int j = 0; j < 4; j++)
                *(float4*)(wS + i + (j << 2)) = *(const float4*)(src + (j << 2));
        }
        __syncthreads();
        #pragma unroll 1
        for (int kk = 0; kk < 64; kk++) {
            ulonglong2 o = *(const ulonglong2*)(buf + (((kc << 6) + kk) << 7) + c0);
            const float* wr = wS + (kk << 8) + s0;
            float4 wa = *(const float4*)(wr);
            float4 wb = *(const float4*)(wr + 4);
            ull w;
            w = pack2(wa.x); fma2(acc[0][0], w, o.x); fma2(acc[0][1], w, o.y);
            w = pack2(wa.y); fma2(acc[1][0], w, o.x); fma2(acc[1][1], w, o.y);
            w = pack2(wa.z); fma2(acc[2][0], w, o.x); fma2(acc[2][1], w, o.y);
            w = pack2(wa.w); fma2(acc[3][0], w, o.x); fma2(acc[3][1], w, o.y);
            w = pack2(wb.x); fma2(acc[4][0], w, o.x); fma2(acc[4][1], w, o.y);
            w = pack2(wb.y); fma2(acc[5][0], w, o.x); fma2(acc[5][1], w, o.y);
            w = pack2(wb.z); fma2(acc[6][0], w, o.x); fma2(acc[6][1], w, o.y);
            w = pack2(wb.w); fma2(acc[7][0], w, o.x); fma2(acc[7][1], w, o.y);
        }
    }
    __syncthreads();   // all pp1 reads of buf done
    #pragma unroll
    for (int m = 0; m < 8; m++) {
        float2 v0 = u2f(acc[m][0]);
        float2 v1 = u2f(acc[m][1]);
        float4 v = make_float4(fmaxf(v0.x, 0.f), fmaxf(v0.y, 0.f),
                               fmaxf(v1.x, 0.f), fmaxf(v1.y, 0.f));
        *(float4*)(buf + ((s0 + m) << 7) + c0) = v;
    }

    // ---- Stage C: pp2 (K=256) -> global out ----
    #pragma unroll
    for (int m = 0; m < 8; m++) {
        ull bv = pack2(b2[s0 + m]);
        acc[m][0] = bv; acc[m][1] = bv;
    }
    #pragma unroll 1
    for (int kc = 0; kc < 4; kc++) {
        __syncthreads();
        {
            int i = tid << 4;
            const float* src = w2T + (kc << 14) + i;
            #pragma unroll
            for (int j = 0; j < 4; j++)
                *(float4*)(wS + i + (j << 2)) = *(const float4*)(src + (j << 2));
        }
        __syncthreads();
        #pragma unroll 1
        for (int kk = 0; kk < 64; kk++) {
            ulonglong2 o = *(const ulonglong2*)(buf + (((kc << 6) + kk) << 7) + c0);
            const float* wr = wS + (kk << 8) + s0;
            float4 wa = *(const float4*)(wr);
            float4 wb = *(const float4*)(wr + 4);
            ull w;
            w = pack2(wa.x); fma2(acc[0][0], w, o.x); fma2(acc[0][1], w, o.y);
            w = pack2(wa.y); fma2(acc[1][0], w, o.x); fma2(acc[1][1], w, o.y);
            w = pack2(wa.z); fma2(acc[2][0], w, o.x); fma2(acc[2][1], w, o.y);
            w = pack2(wa.w); fma2(acc[3][0], w, o.x); fma2(acc[3][1], w, o.y);
            w = pack2(wb.x); fma2(acc[4][0], w, o.x); fma2(acc[4][1], w, o.y);
            w = pack2(wb.y); fma2(acc[5][0], w, o.x); fma2(acc[5][1], w, o.y);
            w = pack2(wb.z); fma2(acc[6][0], w, o.x); fma2(acc[6][1], w, o.y);
            w = pack2(wb.w); fma2(acc[7][0], w, o.x); fma2(acc[7][1], w, o.y);
        }
    }
    {
        const int tgl = t0 + c0;
        #pragma unroll
        for (int m = 0; m < 8; m++) {
            // OUTW odd -> rows not 16B aligned; scalar guarded stores
            float* op = outp + (size_t)((b << 8) + s0 + m) * OUTW + tgl;
            float2 v0 = u2f(acc[m][0]);
            float2 v1 = u2f(acc[m][1]);
            if (tgl < OUTW)     op[0] = v0.x;
            if (tgl + 1 < OUTW) op[1] = v0.y;
            if (tgl + 2 < OUTW) op[2] = v1.x;
            if (tgl + 3 < OUTW) op[3] = v1.y;
        }
    }
}

extern "C" void kernel_launch(void* const* d_in, const int* in_sizes, int n_in,
                              void* d_out, int out_size)
{
    const int*   x        = (const int*)d_in[0];
    const float* causal_w = (const float*)d_in[1];
    const float* causal_b = (const float*)d_in[2];
    const float* filt_w   = (const float*)d_in[3];
    const float* filt_b   = (const float*)d_in[4];
    const float* gate_w   = (const float*)d_in[5];
    const float* gate_b   = (const float*)d_in[6];
    const float* dense_w  = (const float*)d_in[7];
    const float* dense_b  = (const float*)d_in[8];
    const float* skip_w   = (const float*)d_in[9];
    const float* skip_b   = (const float*)d_in[10];
    const float* pp1_w    = (const float*)d_in[11];
    const float* pp1_b    = (const float*)d_in[12];
    const float* pp2_w    = (const float*)d_in[13];
    const float* pp2_b    = (const float*)d_in[14];
    float* out = (float*)d_out;

    float *h0, *h1, *acts, *fgT, *dwTg, *swT, *sbsum, *w1T, *w2T;
    cudaGetSymbolAddress((void**)&h0, g_h0);
    cudaGetSymbolAddress((void**)&h1, g_h1);
    cudaGetSymbolAddress((void**)&acts, g_acts);
    cudaGetSymbolAddress((void**)&fgT, g_fgT);
    cudaGetSymbolAddress((void**)&dwTg, g_dwTg);
    cudaGetSymbolAddress((void**)&swT, g_swT);
    cudaGetSymbolAddress((void**)&sbsum, g_sbsum);
    cudaGetSymbolAddress((void**)&w1T, g_w1T);
    cudaGetSymbolAddress((void**)&w2T, g_w2T);

    static const int dil[NL] = {1, 2, 4, 8, 16, 32, 64, 128, 256, 512,
                                1, 2, 4, 8, 16, 32, 64, 128, 256, 512};

    cudaFuncSetAttribute(layer_kernel,      cudaFuncAttributeMaxDynamicSharedMemorySize, 53760 * 4);
    cudaFuncSetAttribute(causal_kernel,     cudaFuncAttributeMaxDynamicSharedMemorySize, 32768 * 4);
    cudaFuncSetAttribute(fused_post_kernel, cudaFuncAttributeMaxDynamicSharedMemorySize, 57344 * 4);

    // weight prep (feeds layer chain) -- launches 0..1
    {
        dim3 g1(32, NL);
        fgw_prep<<<g1, 256>>>(filt_w, gate_w, fgT);
        dim3 g2(16, NL);
        dw_prep<<<g2, 256>>>(dense_w, dwTg);
    }

    // causal = launch 2; layers start at 3; ncu -s 5 lands on layer #2
    dim3 cg((NT - 1 + 255) / 256, NB);
    causal_kernel<<<cg, 256, 32768 * 4>>>(x, causal_w, causal_b, h0);

    float* hc = h0;
    float* hn = h1;
    int Lh = NT - 1;
    for (int i = 0; i < NL; i++) {
        int d = dil[i];
        int Ti = Lh - d;
        int off = Ti - OUTW;
        dim3 g((Ti + TT - 1) / TT, NB);
        layer_kernel<<<g, 1024, 53760 * 4>>>(
            hc, hn,
            fgT, filt_b + (size_t)i * ND, gate_b + (size_t)i * ND,
            dwTg, dense_b + (size_t)i * NR,
            acts, i, d, Lh, Ti, off);
        float* tmp = hc; hc = hn; hn = tmp;
        Lh = Ti;
    }

    // prep kernels that only feed fused_post run after the layer chain
    transpose_kernel<<<256, 256>>>(pp1_w, w1T);
    transpose_kernel<<<256, 256>>>(pp2_w, w2T);
    skipw_kernel<<<NL * ND, 256>>>(skip_w, swT);
    sbsum_kernel<<<1, 256>>>(skip_b, sbsum);

    dim3 pg((OUTW + 127) / 128, NB);
    fused_post_kernel<<<pg, 1024, 57344 * 4>>>(acts, swT, sbsum,
                                               w1T, pp1_b, w2T, pp2_b, out);
}

// round 16
// speedup vs baseline: 1.0168x; 1.0168x over previous
#include <cuda_runtime.h>
#include <math.h>

#define NB 8
#define NT 16384
#define NQ 256
#define NR 64
#define ND 64
#define NS 256
#define NL 20
#define OUTW 14337
#define OUTW_PAD 14368
#define TT 64
#define AS 68    // act / dwT row stride (16B-aligned rows)

typedef unsigned long long ull;

__device__ __forceinline__ ull pack2(float x) {
    ull r; asm("mov.b64 %0, {%1, %1};" : "=l"(r) : "f"(x)); return r;
}
__device__ __forceinline__ ull pack2(float lo, float hi) {
    ull r; asm("mov.b64 %0, {%1, %2};" : "=l"(r) : "f"(lo), "f"(hi)); return r;
}
__device__ __forceinline__ void fma2(ull& d, ull a, ull b) {
    asm("fma.rn.f32x2 %0, %1, %2, %0;" : "+l"(d) : "l"(a), "l"(b));
}
__device__ __forceinline__ float2 u2f(ull v) {
    float2 f; asm("mov.b64 {%0, %1}, %2;" : "=f"(f.x), "=f"(f.y) : "l"(v)); return f;
}

// Scratch (device globals; no allocation allowed)
__device__ float g_h0[NB * NR * NT];
__device__ float g_h1[NB * NR * NT];
__device__ float g_acts[NL * NB * NR * OUTW_PAD];   // gated activations per layer (skip inputs)
__device__ float g_fgT[NL * 16384];                 // [li][f/g][k][r][dc] -- smem-ready
__device__ float g_dwTg[NL * 4096];                 // [li][dcc][r]
__device__ float g_swT[NL * ND * NS];               // [k=li*64+dc][s]
__device__ float g_sbsum[NS];
__device__ float g_w1T[NS * NS];
__device__ float g_w2T[NQ * NS];

// fgT[li][k*4096 + r*64 + dc] = fw[li][dc][r][k]; g at +8192
__global__ void fgw_prep(const float* __restrict__ fw, const float* __restrict__ gw,
                         float* __restrict__ fgT) {
    int li = blockIdx.y;
    int i = blockIdx.x * 256 + threadIdx.x;    // 0..8191
    int k = i >> 12, r = (i >> 6) & 63, dc = i & 63;
    int src = li * 8192 + dc * 128 + r * 2 + k;
    fgT[li * 16384 + i] = fw[src];
    fgT[li * 16384 + 8192 + i] = gw[src];
}

// dwTg[li][dcc*64 + r] = dw[li][r][dcc]
__global__ void dw_prep(const float* __restrict__ dw, float* __restrict__ dwTg) {
    int li = blockIdx.y;
    int i = blockIdx.x * 256 + threadIdx.x;    // 0..4095
    int dcc = i >> 6, r = i & 63;
    dwTg[li * 4096 + i] = dw[li * 4096 + r * 64 + dcc];
}

// wT[k][s] = w[s][k], 256x256
__global__ void transpose_kernel(const float* __restrict__ w, float* __restrict__ wT) {
    int i = blockIdx.x * 256 + threadIdx.x;
    int k = i >> 8, s = i & 255;
    wT[i] = w[(s << 8) + k];
}

// swT[k][s] = skip_w[li][s][dc], k = li*64+dc
__global__ void skipw_kernel(const float* __restrict__ sw, float* __restrict__ swT) {
    int k = blockIdx.x;          // 0..1279
    int s = threadIdx.x;         // 0..255
    int li = k >> 6, dc = k & 63;
    swT[k * NS + s] = sw[li * (NS * ND) + s * ND + dc];
}

// sbsum[s] = sum_li skip_b[li][s]
__global__ void sbsum_kernel(const float* __restrict__ sb, float* __restrict__ sbsum) {
    int s = threadIdx.x;
    float v = 0.f;
    #pragma unroll
    for (int li = 0; li < NL; li++) v += sb[li * NS + s];
    sbsum[s] = v;
}

// h[b][r][t] = cw[r][x[b,t]][0] + cw[r][x[b,t+1]][1] + cb[r]   (one-hot conv == gather)
__global__ void __launch_bounds__(256) causal_kernel(
    const int* __restrict__ x, const float* __restrict__ cw,
    const float* __restrict__ cb, float* __restrict__ h)
{
    extern __shared__ float sm[];               // 32768 floats: cw [r][q][k]
    __shared__ float cbS[64];
    for (int i = threadIdx.x; i < NR * NQ * 2; i += 256) sm[i] = cw[i];
    if (threadIdx.x < 64) cbS[threadIdx.x] = cb[threadIdx.x];
    __syncthreads();
    int b = blockIdx.y;
    int t = blockIdx.x * 256 + threadIdx.x;
    if (t >= NT - 1) return;
    int q0 = x[b * NT + t] * 2;
    int q1 = x[b * NT + t + 1] * 2 + 1;
    float* hp = h + ((size_t)b << 20) + t;
    #pragma unroll 4
    for (int r = 0; r < 64; r++) {
        hp[r << 14] = sm[(r << 9) + q0] + sm[(r << 9) + q1] + cbS[r];
    }
}

// Fused WaveNet layer, 512 threads, 64 time cols per CTA, 2 CTAs/SM.
// SMEM layout (floats), total 24576 = 98304 B:
//   [0, 8192)       wfT (k,r,dc)   -- dead after phase1 -> act [64][68]
//   [8192, 16384)   wgT (k,r,dc)   -- dead after phase1 -> dwT [64][68]
//   [16384, 20480)  hA  [64][64]
//   [20480, 24576)  hB  [64][64]
// Phase 1: thread tile = 2 dc x 4 time cols (dc-pair-packed weights).
// Phase 2: thread tile = 4 r x 2 time cols (time-packed, dwT broadcast).
__global__ void __launch_bounds__(512, 2) layer_kernel(
    const float* __restrict__ hcur, float* __restrict__ hnext,
    const float* __restrict__ fgT, const float* __restrict__ fb,
    const float* __restrict__ gb,
    const float* __restrict__ dwTg, const float* __restrict__ db,
    float* __restrict__ acts,
    int li, int dil, int Lh, int Ti, int off)
{
    extern __shared__ float smem[];
    float* wfT = smem;
    float* wgT = smem + 8192;
    float* act = smem;              // [64][68], valid after phase1
    float* dwT = smem + 8192;       // [64][68], staged after phase1
    float* hA  = smem + 16384;
    float* hB  = smem + 20480;

    const int tid = threadIdx.x;
    const int b = blockIdx.y;
    const int t0 = blockIdx.x * TT;

    // stage f/g weights: contiguous float4 copy (pre-transposed in global)
    {
        const float4* src = (const float4*)(fgT + li * 16384);
        float4* dst = (float4*)smem;
        #pragma unroll
        for (int j = 0; j < 8; j++)
            dst[tid + (j << 9)] = src[tid + (j << 9)];
    }
    // stage h taps
    const float* hbase = hcur + ((size_t)b << 20);
    #pragma unroll 1
    for (int i = tid << 1; i < 64 * TT; i += 1024) {
        int r = i >> 6, tt = i & 63;
        int ta = t0 + tt;
        float2 va, vb;
        if (ta + 1 < Lh) {
            va = *(const float2*)(hbase + (r << 14) + ta);
        } else {
            va.x = (ta < Lh) ? hbase[(r << 14) + ta] : 0.f;
            va.y = 0.f;
        }
        int tb = ta + dil;
        vb.x = (tb < Lh) ? hbase[(r << 14) + tb] : 0.f;
        vb.y = (tb + 1 < Lh) ? hbase[(r << 14) + tb + 1] : 0.f;
        *(float2*)(hA + i) = va;
        *(float2*)(hB + i) = vb;
    }
    __syncthreads();

    // ---- Phase 1: filter/gate GEMM (K=64, 2 taps), 2dc x 4cols ----
    const int cg = tid & 15;         // col group (4 cols)
    const int dgp = tid >> 4;        // 0..31 : dc pair
    const int dc0 = dgp << 1;
    const int cols = cg << 2;
    ull facc[4], gacc[4];            // [col], dc-pair packed
    {
        ull fb2 = pack2(fb[dc0], fb[dc0 + 1]);
        ull gb2 = pack2(gb[dc0], gb[dc0 + 1]);
        #pragma unroll
        for (int c = 0; c < 4; c++) { facc[c] = fb2; gacc[c] = gb2; }
        const float* hap = hA + cols;
        const float* hbp = hB + cols;
        #pragma unroll 4
        for (int r = 0; r < 64; r++) {
            float4 A = *(const float4*)(hap + (r << 6));
            float4 C = *(const float4*)(hbp + (r << 6));
            ull a[4], c2[4];
            a[0] = pack2(A.x); a[1] = pack2(A.y); a[2] = pack2(A.z); a[3] = pack2(A.w);
            c2[0] = pack2(C.x); c2[1] = pack2(C.y); c2[2] = pack2(C.z); c2[3] = pack2(C.w);
            ull Wf0 = *(const ull*)(wfT + (r << 6) + dc0);
            ull Wf1 = *(const ull*)(wfT + 4096 + (r << 6) + dc0);
            ull Wg0 = *(const ull*)(wgT + (r << 6) + dc0);
            ull Wg1 = *(const ull*)(wgT + 4096 + (r << 6) + dc0);
            #pragma unroll
            for (int c = 0; c < 4; c++) {
                fma2(facc[c], Wf0, a[c]);
                fma2(facc[c], Wf1, c2[c]);
                fma2(gacc[c], Wg0, a[c]);
                fma2(gacc[c], Wg1, c2[c]);
            }
        }
        // out = tanh(f) * sigmoid(g)   (lanes are the 2 channels)
        #pragma unroll
        for (int c = 0; c < 4; c++) {
            float2 f = u2f(facc[c]);
            float2 g = u2f(gacc[c]);
            float ef0 = __expf(fminf(-2.f * f.x, 80.f));
            float ef1 = __expf(fminf(-2.f * f.y, 80.f));
            float eg0 = __expf(fminf(-g.x, 80.f));
            float eg1 = __expf(fminf(-g.y, 80.f));
            float o0 = __fdividef(1.f - ef0, (1.f + ef0) * (1.f + eg0));
            float o1 = __fdividef(1.f - ef1, (1.f + ef1) * (1.f + eg1));
            facc[c] = pack2(o0, o1);
        }
    }
    __syncthreads();    // all wfT/wgT/hA reads done

    // write act tile (rows dc0, dc0+1; cols cols..cols+3); stage dwT into wgT region
    {
        float2 f0 = u2f(facc[0]), f1 = u2f(facc[1]),
               f2 = u2f(facc[2]), f3 = u2f(facc[3]);
        *(float4*)(act + dc0 * AS + cols)       = make_float4(f0.x, f1.x, f2.x, f3.x);
        *(float4*)(act + (dc0 + 1) * AS + cols) = make_float4(f0.y, f1.y, f2.y, f3.y);
        #pragma unroll
        for (int j = 0; j < 2; j++) {
            int idx = tid + (j << 9);    // 0..1023
            float4 v = ((const float4*)(dwTg + li * 4096))[idx];
            int dcc = idx >> 4, r4 = (idx & 15) << 2;
            *(float4*)(dwT + dcc * AS + r4) = v;
        }
    }
    __syncthreads();

    // store act tile to global (skip input), cols >= off
    {
        float* abase = acts + (size_t)((li * NB + b) * 64) * OUTW_PAD - off;
        #pragma unroll 1
        for (int i = tid; i < 64 * TT; i += 512) {
            int dcw = i >> 6, tt = i & 63;
            int tgl = t0 + tt;
            if (tgl >= off && tgl < Ti)
                abase[(size_t)dcw * OUTW_PAD + tgl] = act[dcw * AS + tt];
        }
    }

    const int tl = tid & 31;
    const int wp = tid >> 5;   // 0..15

    // ---- Phase 2: dense 1x1 (D->R) + residual -> hnext, 4r x 2cols ----
    {
        const int r0 = wp << 2;
        const int c0 = tl << 1;
        ull acc[4];
        #pragma unroll
        for (int m = 0; m < 4; m++) acc[m] = pack2(db[r0 + m]);
        #pragma unroll 2
        for (int dcc = 0; dcc < 64; dcc++) {
            ull o = *(const ull*)(act + dcc * AS + c0);
            float4 w4 = *(const float4*)(dwT + dcc * AS + r0);   // broadcast
            fma2(acc[0], pack2(w4.x), o);
            fma2(acc[1], pack2(w4.y), o);
            fma2(acc[2], pack2(w4.z), o);
            fma2(acc[3], pack2(w4.w), o);
        }
        float* hnb = hnext + ((size_t)b << 20);
        const int tgl = t0 + c0;
        #pragma unroll
        for (int m = 0; m < 4; m++) {
            int r = r0 + m;
            float2 hv = *(const float2*)(hB + (r << 6) + c0);
            float2 v = u2f(acc[m]);
            v.x += hv.x; v.y += hv.y;
            if (tgl + 1 < Ti) {
                *(float2*)(hnb + (r << 14) + tgl) = v;
            } else if (tgl < Ti) {
                hnb[(r << 14) + tgl] = v.x;
            }
        }
    }
}

// Fused post chain: total(K=1280 GEMM over acts) -> +sbsum,relu -> pp1(K=256)
//   -> +b1,relu -> pp2(K=256) -> +b2 -> out.   1024 threads, 128 time cols/CTA.
// Thread tile: 8 s x 4 consecutive t (time-packed); weights broadcast LDS.128.
// smem: inS [64][128]=8192, wS [64][256]=16384, buf [256][128]=32768 -> 57344 floats
__global__ void __launch_bounds__(1024) fused_post_kernel(
    const float* __restrict__ acts, const float* __restrict__ swT,
    const float* __restrict__ sbsum,
    const float* __restrict__ w1T, const float* __restrict__ b1,
    const float* __restrict__ w2T, const float* __restrict__ b2,
    float* __restrict__ outp)
{
    extern __shared__ float smem[];
    float* inS = smem;            // [64][128]
    float* wS  = smem + 8192;     // [64][256]
    float* buf = smem + 24576;    // [256][128]
    const int tid = threadIdx.x;
    const int b = blockIdx.y;
    const int t0 = blockIdx.x << 7;
    const int tl = tid & 31;
    const int wp = tid >> 5;      // 0..31
    const int s0 = wp << 3;       // 8 s per thread (broadcast weight quads in warp)
    const int c0 = tl << 2;       // 4 consecutive t per lane
    const bool fullTile = (t0 + 127 < OUTW);

    ull acc[8][2];

    // ---- Stage A: skip GEMM, K = 20 layers x 64 channels ----
    #pragma unroll
    for (int m = 0; m < 8; m++) { acc[m][0] = 0ULL; acc[m][1] = 0ULL; }

    #pragma unroll 1
    for (int li = 0; li < NL; li++) {
        __syncthreads();
        const float* ab = acts + (size_t)((li * NB + b) * 64) * OUTW_PAD;
        if (fullTile) {
            int i = tid << 3;
            int dcr = i >> 7, tt = i & 127;
            const float* src = ab + (size_t)dcr * OUTW_PAD + t0 + tt;
            *(float4*)(inS + i)     = *(const float4*)(src);
            *(float4*)(inS + i + 4) = *(const float4*)(src + 4);
        } else {
            #pragma unroll 1
            for (int i = tid; i < 8192; i += 1024) {
                int dcr = i >> 7, tt = i & 127;
                int t = t0 + tt;
                inS[i] = (t < OUTW) ? ab[(size_t)dcr * OUTW_PAD + t] : 0.f;
            }
        }
        {
            int i = tid << 4;
            const float* src = swT + li * 16384 + i;
            #pragma unroll
            for (int j = 0; j < 4; j++)
                *(float4*)(wS + i + (j << 2)) = *(const float4*)(src + (j << 2));
        }
        __syncthreads();
        #pragma unroll 1
        for (int kk = 0; kk < 64; kk++) {
            ulonglong2 o = *(const ulonglong2*)(inS + (kk << 7) + c0);
            const float* wr = wS + (kk << 8) + s0;
            float4 wa = *(const float4*)(wr);       // broadcast
            float4 wb = *(const float4*)(wr + 4);   // broadcast
            ull w;
            w = pack2(wa.x); fma2(acc[0][0], w, o.x); fma2(acc[0][1], w, o.y);
            w = pack2(wa.y); fma2(acc[1][0], w, o.x); fma2(acc[1][1], w, o.y);
            w = pack2(wa.z); fma2(acc[2][0], w, o.x); fma2(acc[2][1], w, o.y);
            w = pack2(wa.w); fma2(acc[3][0], w, o.x); fma2(acc[3][1], w, o.y);
            w = pack2(wb.x); fma2(acc[4][0], w, o.x); fma2(acc[4][1], w, o.y);
            w = pack2(wb.y); fma2(acc[5][0], w, o.x); fma2(acc[5][1], w, o.y);
            w = pack2(wb.z); fma2(acc[6][0], w, o.x); fma2(acc[6][1], w, o.y);
            w = pack2(wb.w); fma2(acc[7][0], w, o.x); fma2(acc[7][1], w, o.y);
        }
    }
    // total + biasSum, relu -> buf
    #pragma unroll
    for (int m = 0; m < 8; m++) {
        float sbv = sbsum[s0 + m];
        float2 v0 = u2f(acc[m][0]);
        float2 v1 = u2f(acc[m][1]);
        float4 v = make_float4(fmaxf(v0.x + sbv, 0.f), fmaxf(v0.y + sbv, 0.f),
                               fmaxf(v1.x + sbv, 0.f), fmaxf(v1.y + sbv, 0.f));
        *(float4*)(buf + ((s0 + m) << 7) + c0) = v;
    }

    // ---- Stage B: pp1 (K=256) ----
    #pragma unroll
    for (int m = 0; m < 8; m++) {
        ull bv = pack2(b1[s0 + m]);
        acc[m][0] = bv; acc[m][1] = bv;
    }
    #pragma unroll 1
    for (int kc = 0; kc < 4; kc++) {
        __syncthreads();
        {
            int i = tid << 4;
            const float* src = w1T + (kc << 14) + i;
            #pragma unroll
            for (int j = 0; j < 4; j++)
                *(float4*)(wS + i + (j << 2)) = *(const float4*)(src + (j << 2));
        }
        __syncthreads();
        #pragma unroll 1
        for (int kk = 0; kk < 64; kk++) {
            ulonglong2 o = *(const ulonglong2*)(buf + (((kc << 6) + kk) << 7) + c0);
            const float* wr = wS + (kk << 8) + s0;
            float4 wa = *(const float4*)(wr);
            float4 wb = *(const float4*)(wr + 4);
            ull w;
            w = pack2(wa.x); fma2(acc[0][0], w, o.x); fma2(acc[0][1], w, o.y);
            w = pack2(wa.y); fma2(acc[1][0], w, o.x); fma2(acc[1][1], w, o.y);
            w = pack2(wa.z); fma2(acc[2][0], w, o.x); fma2(acc[2][1], w, o.y);
            w = pack2(wa.w); fma2(acc[3][0], w, o.x); fma2(acc[3][1], w, o.y);
            w = pack2(wb.x); fma2(acc[4][0], w, o.x); fma2(acc[4][1], w, o.y);
            w = pack2(wb.y); fma2(acc[5][0], w, o.x); fma2(acc[5][1], w, o.y);
            w = pack2(wb.z); fma2(acc[6][0], w, o.x); fma2(acc[6][1], w, o.y);
            w = pack2(wb.w); fma2(acc[7][0], w, o.x); fma2(acc[7][1], w, o.y);
        }
    }
    __syncthreads();   // all pp1 reads of buf done
    #pragma unroll
    for (int m = 0; m < 8; m++) {
        float2 v0 = u2f(acc[m][0]);
        float2 v1 = u2f(acc[m][1]);
        float4 v = make_float4(fmaxf(v0.x, 0.f), fmaxf(v0.y, 0.f),
                               fmaxf(v1.x, 0.f), fmaxf(v1.y, 0.f));
        *(float4*)(buf + ((s0 + m) << 7) + c0) = v;
    }

    // ---- Stage C: pp2 (K=256) -> global out ----
    #pragma unroll
    for (int m = 0; m < 8; m++) {
        ull bv = pack2(b2[s0 + m]);
        acc[m][0] = bv; acc[m][1] = bv;
    }
    #pragma unroll 1
    for (int kc = 0; kc < 4; kc++) {
        __syncthreads();
        {
            int i = tid << 4;
            const float* src = w2T + (kc << 14) + i;
            #pragma unroll
            for (int j = 0; j < 4; j++)
                *(float4*)(wS + i + (j << 2)) = *(const float4*)(src + (j << 2));
        }
        __syncthreads();
        #pragma unroll 1
        for (int kk = 0; kk < 64; kk++) {
            ulonglong2 o = *(const ulonglong2*)(buf + (((kc << 6) + kk) << 7) + c0);
            const float* wr = wS + (kk << 8) + s0;
            float4 wa = *(const float4*)(wr);
            float4 wb = *(const float4*)(wr + 4);
            ull w;
            w = pack2(wa.x); fma2(acc[0][0], w, o.x); fma2(acc[0][1], w, o.y);
            w = pack2(wa.y); fma2(acc[1][0], w, o.x); fma2(acc[1][1], w, o.y);
            w = pack2(wa.z); fma2(acc[2][0], w, o.x); fma2(acc[2][1], w, o.y);
            w = pack2(wa.w); fma2(acc[3][0], w, o.x); fma2(acc[3][1], w, o.y);
            w = pack2(wb.x); fma2(acc[4][0], w, o.x); fma2(acc[4][1], w, o.y);
            w = pack2(wb.y); fma2(acc[5][0], w, o.x); fma2(acc[5][1], w, o.y);
            w = pack2(wb.z); fma2(acc[6][0], w, o.x); fma2(acc[6][1], w, o.y);
            w = pack2(wb.w); fma2(acc[7][0], w, o.x); fma2(acc[7][1], w, o.y);
        }
    }
    {
        const int tgl = t0 + c0;
        #pragma unroll
        for (int m = 0; m < 8; m++) {
            // OUTW odd -> rows not 16B aligned; scalar guarded stores
            float* op = outp + (size_t)((b << 8) + s0 + m) * OUTW + tgl;
            float2 v0 = u2f(acc[m][0]);
            float2 v1 = u2f(acc[m][1]);
            if (tgl < OUTW)     op[0] = v0.x;
            if (tgl + 1 < OUTW) op[1] = v0.y;
            if (tgl + 2 < OUTW) op[2] = v1.x;
            if (tgl + 3 < OUTW) op[3] = v1.y;
        }
    }
}

extern "C" void kernel_launch(void* const* d_in, const int* in_sizes, int n_in,
                              void* d_out, int out_size)
{
    const int*   x        = (const int*)d_in[0];
    const float* causal_w = (const float*)d_in[1];
    const float* causal_b = (const float*)d_in[2];
    const float* filt_w   = (const float*)d_in[3];
    const float* filt_b   = (const float*)d_in[4];
    const float* gate_w   = (const float*)d_in[5];
    const float* gate_b   = (const float*)d_in[6];
    const float* dense_w  = (const float*)d_in[7];
    const float* dense_b  = (const float*)d_in[8];
    const float* skip_w   = (const float*)d_in[9];
    const float* skip_b   = (const float*)d_in[10];
    const float* pp1_w    = (const float*)d_in[11];
    const float* pp1_b    = (const float*)d_in[12];
    const float* pp2_w    = (const float*)d_in[13];
    const float* pp2_b    = (const float*)d_in[14];
    float* out = (float*)d_out;

    float *h0, *h1, *acts, *fgT, *dwTg, *swT, *sbsum, *w1T, *w2T;
    cudaGetSymbolAddress((void**)&h0, g_h0);
    cudaGetSymbolAddress((void**)&h1, g_h1);
    cudaGetSymbolAddress((void**)&acts, g_acts);
    cudaGetSymbolAddress((void**)&fgT, g_fgT);
    cudaGetSymbolAddress((void**)&dwTg, g_dwTg);
    cudaGetSymbolAddress((void**)&swT, g_swT);
    cudaGetSymbolAddress((void**)&sbsum, g_sbsum);
    cudaGetSymbolAddress((void**)&w1T, g_w1T);
    cudaGetSymbolAddress((void**)&w2T, g_w2T);

    static const int dil[NL] = {1, 2, 4, 8, 16, 32, 64, 128, 256, 512,
                                1, 2, 4, 8, 16, 32, 64, 128, 256, 512};

    cudaFuncSetAttribute(layer_kernel,      cudaFuncAttributeMaxDynamicSharedMemorySize, 24576 * 4);
    cudaFuncSetAttribute(causal_kernel,     cudaFuncAttributeMaxDynamicSharedMemorySize, 32768 * 4);
    cudaFuncSetAttribute(fused_post_kernel, cudaFuncAttributeMaxDynamicSharedMemorySize, 57344 * 4);

    // weight prep (feeds layer chain) -- launches 0..1
    {
        dim3 g1(32, NL);
        fgw_prep<<<g1, 256>>>(filt_w, gate_w, fgT);
        dim3 g2(16, NL);
        dw_prep<<<g2, 256>>>(dense_w, dwTg);
    }

    // causal = launch 2; layers start at 3; ncu -s 5 lands on layer #2
    dim3 cg((NT - 1 + 255) / 256, NB);
    causal_kernel<<<cg, 256, 32768 * 4>>>(x, causal_w, causal_b, h0);

    float* hc = h0;
    float* hn = h1;
    int Lh = NT - 1;
    for (int i = 0; i < NL; i++) {
        int d = dil[i];
        int Ti = Lh - d;
        int off = Ti - OUTW;
        dim3 g((Ti + TT - 1) / TT, NB);
        layer_kernel<<<g, 512, 24576 * 4>>>(
            hc, hn,
            fgT, filt_b + (size_t)i * ND, gate_b + (size_t)i * ND,
            dwTg, dense_b + (size_t)i * NR,
            acts, i, d, Lh, Ti, off);
        float* tmp = hc; hc = hn; hn = tmp;
        Lh = Ti;
    }

    // prep kernels that only feed fused_post run after the layer chain
    transpose_kernel<<<256, 256>>>(pp1_w, w1T);
    transpose_kernel<<<256, 256>>>(pp2_w, w2T);
    skipw_kernel<<<NL * ND, 256>>>(skip_w, swT);
    sbsum_kernel<<<1, 256>>>(skip_b, sbsum);

    dim3 pg((OUTW + 127) / 128, NB);
    fused_post_kernel<<<pg, 1024, 57344 * 4>>>(acts, swT, sbsum,
                                               w1T, pp1_b, w2T, pp2_b, out);
}